// round 2
// baseline (speedup 1.0000x reference)
#include <cuda_runtime.h>
#include <stdint.h>

// Segmented max pooling:
//   out[seg, c] = max over rows r with vt_map[r]==seg of in[r, c]; empty -> 0
//
// NOTE: vt_map / vt_replace are int32 (JAX downcasts int64 without x64 mode).
//
// Float max via monotone unsigned key:
//   key(f): b = bits(f); b has sign bit -> ~b ; else b | 0x80000000
//   Strictly increasing in f, so atomicMax on keys == float max.

__device__ __forceinline__ unsigned fkey(float f) {
    unsigned b = __float_as_uint(f);
    return (b & 0x80000000u) ? ~b : (b | 0x80000000u);
}

__device__ __forceinline__ float fdecode(unsigned k) {
    unsigned b = (k & 0x80000000u) ? (k & 0x7FFFFFFFu) : ~k;
    return __uint_as_float(b);
}

// key(-inf) = ~0xFF800000 = 0x007FFFFF
#define INIT_KEY 0x007FFFFFu

__global__ void init_out_kernel(uint4* out4, long n4) {
    long i = blockIdx.x * (long)blockDim.x + threadIdx.x;
    long stride = gridDim.x * (long)blockDim.x;
    uint4 v = make_uint4(INIT_KEY, INIT_KEY, INIT_KEY, INIT_KEY);
    for (; i < n4; i += stride) out4[i] = v;
}

// One iteration = one float4 (4 consecutive channels of one row).
// C divisible by 4 (C=64 here).
__global__ void scatter_max_kernel(const float4* __restrict__ in4,
                                   const int* __restrict__ vt_map,
                                   unsigned* __restrict__ out,
                                   long n4_total, int c4, int vt_out) {
    long i = blockIdx.x * (long)blockDim.x + threadIdx.x;
    long stride = gridDim.x * (long)blockDim.x;
    for (; i < n4_total; i += stride) {
        long row = i / c4;
        int  q   = (int)(i - row * c4);      // which float4 within the row
        int seg = vt_map[row];
        if (seg < 0 || seg >= vt_out) continue;
        float4 v = in4[i];
        unsigned* o = out + (size_t)seg * (size_t)(c4 * 4) + (size_t)q * 4;
        atomicMax(o + 0, fkey(v.x));
        atomicMax(o + 1, fkey(v.y));
        atomicMax(o + 2, fkey(v.z));
        atomicMax(o + 3, fkey(v.w));
    }
}

__global__ void fixup_kernel(uint4* __restrict__ out4, long n4) {
    long i = blockIdx.x * (long)blockDim.x + threadIdx.x;
    long stride = gridDim.x * (long)blockDim.x;
    for (; i < n4; i += stride) {
        uint4 k = out4[i];
        float4 f;
        f.x = (k.x == INIT_KEY) ? 0.0f : fdecode(k.x);
        f.y = (k.y == INIT_KEY) ? 0.0f : fdecode(k.y);
        f.z = (k.z == INIT_KEY) ? 0.0f : fdecode(k.z);
        f.w = (k.w == INIT_KEY) ? 0.0f : fdecode(k.w);
        *reinterpret_cast<float4*>(out4 + i) = f;
    }
}

extern "C" void kernel_launch(void* const* d_in, const int* in_sizes, int n_in,
                              void* d_out, int out_size) {
    const float* inputs = (const float*)d_in[0];
    // d_in[1] = vt_replace (unused for max pooling)
    const int*   vt_map = (const int*)d_in[2];

    long n_in_elems = in_sizes[0];        // N_IN * C
    long n_rows     = in_sizes[2];        // N_IN (vt_map length)
    int  C          = (int)(n_in_elems / n_rows);   // 64
    int  vt_out     = out_size / C;                 // 262144

    long out_n4 = (long)out_size / 4;
    long in_n4  = n_in_elems / 4;
    int  c4     = C / 4;

    const int TPB = 256;
    int blocks = 148 * 16;

    init_out_kernel<<<blocks, TPB>>>((uint4*)d_out, out_n4);
    scatter_max_kernel<<<blocks * 2, TPB>>>((const float4*)inputs, vt_map,
                                            (unsigned*)d_out, in_n4, c4, vt_out);
    fixup_kernel<<<blocks, TPB>>>((uint4*)d_out, out_n4);
}

// round 3
// speedup vs baseline: 1.6236x; 1.6236x over previous
#include <cuda_runtime.h>
#include <stdint.h>

// Segmented max pooling, gather formulation:
//   1) histogram vt_map -> counts          (1M int atomics, spread)
//   2) exclusive scan counts -> offsets    (3 tiny kernels)
//   3) fill CSR row-id buckets             (1M int atomics)
//   4) gather: 1 warp per segment, max over its rows, write (0 if empty)
// Falls back to the atomic-scatter path if shapes exceed static scratch.

#define MAX_SEG   (1 << 18)   // 262144
#define MAX_ROWS  (1 << 20)   // 1048576
#define SCAN_CHUNK 1024
#define NEG_INF __int_as_float(0xff800000)

__device__ int g_counts[MAX_SEG];
__device__ int g_cursor[MAX_SEG];
__device__ int g_offsets[MAX_SEG];
__device__ int g_rows[MAX_ROWS];
__device__ int g_chunksums[1024];

// ---------------- gather path ----------------

__global__ void zero_kernel(int nseg) {
    int i = blockIdx.x * blockDim.x + threadIdx.x;
    int stride = gridDim.x * blockDim.x;
    for (; i < nseg; i += stride) { g_counts[i] = 0; g_cursor[i] = 0; }
}

__global__ void count_kernel(const int* __restrict__ vt_map, int n_rows, int vt_out) {
    int i = blockIdx.x * blockDim.x + threadIdx.x;
    if (i >= n_rows) return;
    int seg = vt_map[i];
    if (seg >= 0 && seg < vt_out) atomicAdd(&g_counts[seg], 1);
}

// Per-chunk exclusive scan: each block scans SCAN_CHUNK counts (4/thread),
// writes exclusive offsets (local) and the chunk total.
__global__ void scan_chunks_kernel(int nseg) {
    __shared__ int s[256];
    int tid = threadIdx.x;
    int base = blockIdx.x * SCAN_CHUNK + tid * 4;
    int v[4];
    #pragma unroll
    for (int k = 0; k < 4; k++)
        v[k] = (base + k < nseg) ? g_counts[base + k] : 0;
    int tot = v[0] + v[1] + v[2] + v[3];
    s[tid] = tot;
    __syncthreads();
    // Hillis-Steele inclusive scan over 256 thread-totals
    #pragma unroll
    for (int d = 1; d < 256; d <<= 1) {
        int add = (tid >= d) ? s[tid - d] : 0;
        __syncthreads();
        s[tid] += add;
        __syncthreads();
    }
    int excl = s[tid] - tot;     // exclusive prefix of this thread's group
    int run = excl;
    #pragma unroll
    for (int k = 0; k < 4; k++) {
        if (base + k < nseg) g_offsets[base + k] = run;
        run += v[k];
    }
    if (tid == 255) g_chunksums[blockIdx.x] = s[255];
}

// Single-block exclusive scan of chunk sums (up to 1024 chunks).
__global__ void scan_sums_kernel(int nchunks) {
    __shared__ int s[1024];
    int tid = threadIdx.x;
    int v = (tid < nchunks) ? g_chunksums[tid] : 0;
    s[tid] = v;
    __syncthreads();
    #pragma unroll
    for (int d = 1; d < 1024; d <<= 1) {
        int add = (tid >= d) ? s[tid - d] : 0;
        __syncthreads();
        s[tid] += add;
        __syncthreads();
    }
    if (tid < nchunks) g_chunksums[tid] = s[tid] - v;  // exclusive
}

__global__ void add_back_kernel(int nseg) {
    int i = blockIdx.x * blockDim.x + threadIdx.x;
    int stride = gridDim.x * blockDim.x;
    for (; i < nseg; i += stride)
        g_offsets[i] += g_chunksums[i / SCAN_CHUNK];
}

__global__ void fill_kernel(const int* __restrict__ vt_map, int n_rows, int vt_out) {
    int i = blockIdx.x * blockDim.x + threadIdx.x;
    if (i >= n_rows) return;
    int seg = vt_map[i];
    if (seg >= 0 && seg < vt_out) {
        int pos = atomicAdd(&g_cursor[seg], 1);
        g_rows[g_offsets[seg] + pos] = i;
    }
}

// One warp per segment; C == 64: lane handles one float2 (channels 2l, 2l+1).
__global__ void gather_max_kernel(const float2* __restrict__ in2,
                                  float2* __restrict__ out2, int nseg) {
    int warp = (blockIdx.x * blockDim.x + threadIdx.x) >> 5;
    int lane = threadIdx.x & 31;
    if (warp >= nseg) return;
    int off = g_offsets[warp];
    int cnt = g_counts[warp];
    float2 acc = make_float2(NEG_INF, NEG_INF);
    int j = 0;
    // unroll-by-2 for extra MLP
    for (; j + 2 <= cnt; j += 2) {
        int r0 = __ldg(&g_rows[off + j]);
        int r1 = __ldg(&g_rows[off + j + 1]);
        float2 a = __ldg(&in2[(size_t)r0 * 32 + lane]);
        float2 b = __ldg(&in2[(size_t)r1 * 32 + lane]);
        acc.x = fmaxf(acc.x, fmaxf(a.x, b.x));
        acc.y = fmaxf(acc.y, fmaxf(a.y, b.y));
    }
    if (j < cnt) {
        int r0 = __ldg(&g_rows[off + j]);
        float2 a = __ldg(&in2[(size_t)r0 * 32 + lane]);
        acc.x = fmaxf(acc.x, a.x);
        acc.y = fmaxf(acc.y, a.y);
    }
    if (cnt == 0) acc = make_float2(0.0f, 0.0f);
    out2[(size_t)warp * 32 + lane] = acc;
}

// ---------------- fallback scatter path (generic) ----------------

__device__ __forceinline__ unsigned fkey(float f) {
    unsigned b = __float_as_uint(f);
    return (b & 0x80000000u) ? ~b : (b | 0x80000000u);
}
__device__ __forceinline__ float fdecode(unsigned k) {
    unsigned b = (k & 0x80000000u) ? (k & 0x7FFFFFFFu) : ~k;
    return __uint_as_float(b);
}
#define INIT_KEY 0x007FFFFFu

__global__ void init_out_kernel(unsigned* out, long n) {
    long i = blockIdx.x * (long)blockDim.x + threadIdx.x;
    long stride = gridDim.x * (long)blockDim.x;
    for (; i < n; i += stride) out[i] = INIT_KEY;
}

__global__ void scatter_max_kernel(const float* __restrict__ in,
                                   const int* __restrict__ vt_map,
                                   unsigned* __restrict__ out,
                                   long n_total, int C, int vt_out) {
    long i = blockIdx.x * (long)blockDim.x + threadIdx.x;
    long stride = gridDim.x * (long)blockDim.x;
    for (; i < n_total; i += stride) {
        long row = i / C;
        int  c   = (int)(i - row * C);
        int seg = vt_map[row];
        if (seg < 0 || seg >= vt_out) continue;
        atomicMax(out + (size_t)seg * C + c, fkey(in[i]));
    }
}

__global__ void fixup_kernel(unsigned* __restrict__ out, long n) {
    long i = blockIdx.x * (long)blockDim.x + threadIdx.x;
    long stride = gridDim.x * (long)blockDim.x;
    for (; i < n; i += stride) {
        unsigned k = out[i];
        float f = (k == INIT_KEY) ? 0.0f : fdecode(k);
        out[i] = __float_as_uint(f);
    }
}

// ---------------- launcher ----------------

extern "C" void kernel_launch(void* const* d_in, const int* in_sizes, int n_in,
                              void* d_out, int out_size) {
    const float* inputs = (const float*)d_in[0];
    // d_in[1] = vt_replace (unused for max pooling)
    const int*   vt_map = (const int*)d_in[2];

    long n_in_elems = in_sizes[0];                 // N_IN * C
    int  n_rows     = in_sizes[2];                 // N_IN
    int  C          = (int)(n_in_elems / n_rows);  // 64
    int  vt_out     = out_size / C;                // 262144

    const int TPB = 256;

    if (C == 64 && vt_out <= MAX_SEG && n_rows <= MAX_ROWS && (vt_out % 1) == 0) {
        int nseg = vt_out;
        int nchunks = (nseg + SCAN_CHUNK - 1) / SCAN_CHUNK;   // 256 here

        zero_kernel<<<256, TPB>>>(nseg);
        count_kernel<<<(n_rows + TPB - 1) / TPB, TPB>>>(vt_map, n_rows, vt_out);
        scan_chunks_kernel<<<nchunks, 256>>>(nseg);
        scan_sums_kernel<<<1, 1024>>>(nchunks);
        add_back_kernel<<<256, TPB>>>(nseg);
        fill_kernel<<<(n_rows + TPB - 1) / TPB, TPB>>>(vt_map, n_rows, vt_out);

        int warps_per_block = TPB / 32;
        int gblocks = (nseg + warps_per_block - 1) / warps_per_block;
        gather_max_kernel<<<gblocks, TPB>>>((const float2*)inputs,
                                            (float2*)d_out, nseg);
    } else {
        long out_elems = (long)out_size;
        int blocks = 148 * 16;
        init_out_kernel<<<blocks, TPB>>>((unsigned*)d_out, out_elems);
        scatter_max_kernel<<<blocks * 2, TPB>>>(inputs, vt_map,
                                                (unsigned*)d_out, n_in_elems, C, vt_out);
        fixup_kernel<<<blocks, TPB>>>((unsigned*)d_out, out_elems);
    }
}